// round 15
// baseline (speedup 1.0000x reference)
#include <cuda_runtime.h>
#include <cuda_bf16.h>
#include <cuda_fp16.h>
#include <cstdint>

// ============================================================================
// softassignment on B200 (sm_100a), round 15 (= round-14 source; round-14
// bench died to an infra container failure before any HW evidence existed).
//   out = intranorm( softmax(alpha*<x_b, zhat_bk>) @ zhat_b )
//   - softmax(a*dot) identity; denominator cancels in final L2 norm.
//   - exp on the SFU pipe (ex2.approx.ftz)            [R9 win]
//   - GEMM2 single fp16 MMA, online row-max rescaling [R13 win: 135.5us]
// Round-14/15 delta — R13 profile shows NO busy pipe (tensor 47%, issue 42%):
// the chunk loop serializes GEMM1 -> max(2 dependent SHFLs) -> exp -> GEMM2.
// Software-pipeline: fully unroll the 4 chunks and issue GEMM1(c+1)'s 24
// independent MMAs BEFORE process(c); in-order issue + scoreboard completion
// means the tensor pipe runs chunk c+1's GEMM1 while scalar pipes do chunk
// c's max/exp. Second C block costs +32 regs -> __launch_bounds__(256,2)
// (128-reg cap, 16 warps/SM). Evidence says ILP-bound, not occupancy-bound.
// ============================================================================

#define NBOOK 16
#define DIMS  16
#define KCW   256
#define FDIM  256
#define L2E   1.4426950408889634f

// g_p1 (GEMM1 B, bf16 hi/lo): [book][cw][ti] 16B, one LDS.128 = 4 fragments.
// g_p2 (GEMM2 B, fp16):       [book][d<8][m][ti] 16B =
//   {f16x2(z[d][16m+2ti..]), f16x2(z[d][16m+2ti+8..]), same for d+8}
__device__ uint4 g_p1[NBOOK * KCW * 4];
__device__ uint4 g_p2[NBOOK * 512];

// ---------------------------------------------------------------------------
__global__ void prep_z_kernel(const float* __restrict__ Zw) {
    int b = blockIdx.x, cw = threadIdx.x;
    const float* src = Zw + cw * FDIM + b * DIMS;
    float v[DIMS], ss = 0.f;
#pragma unroll
    for (int d = 0; d < DIMS; d++) { v[d] = src[d]; ss = fmaf(v[d], v[d], ss); }
    float inv = rsqrtf(fmaxf(ss, 1e-24f));   // == 1/clip(norm,1e-12)
    float z[DIMS];
    __nv_bfloat16 h[DIMS], l[DIMS];
#pragma unroll
    for (int d = 0; d < DIMS; d++) {
        z[d] = v[d] * inv;
        h[d] = __float2bfloat16(z[d]);
        l[d] = __float2bfloat16(z[d] - __bfloat162float(h[d]));
    }
    __nv_bfloat16* p1 = (__nv_bfloat16*)(g_p1 + (b * KCW + cw) * 4);
#pragma unroll
    for (int ti = 0; ti < 4; ti++) {
        p1[ti * 8 + 0] = h[2 * ti];     p1[ti * 8 + 1] = h[2 * ti + 1];
        p1[ti * 8 + 2] = h[2 * ti + 8]; p1[ti * 8 + 3] = h[2 * ti + 9];
        p1[ti * 8 + 4] = l[2 * ti];     p1[ti * 8 + 5] = l[2 * ti + 1];
        p1[ti * 8 + 6] = l[2 * ti + 8]; p1[ti * 8 + 7] = l[2 * ti + 9];
    }
    // GEMM2 fp16 packing: cw = 16m + r; slot = (r&1)+((r>>3)<<1) encodes
    // k-order {2ti, 2ti+1, 2ti+8, 2ti+9}.
    int m = cw >> 4, r = cw & 15;
    int tj = (r >> 1) & 3;
    int slot = (r & 1) + ((r >> 3) << 1);
#pragma unroll
    for (int d = 0; d < 8; d++) {
        __half* q = (__half*)(g_p2 + ((b * 8 + d) * 16 + m) * 4 + tj);
        q[slot]     = __float2half_rn(z[d]);
        q[slot + 4] = __float2half_rn(z[d + 8]);
    }
}

// ---------------------------------------------------------------------------
__device__ __forceinline__ void mma16816(float* c, const unsigned* a,
                                         unsigned b0, unsigned b1) {
    asm("mma.sync.aligned.m16n8k16.row.col.f32.bf16.bf16.f32 "
        "{%0,%1,%2,%3}, {%4,%5,%6,%7}, {%8,%9}, {%0,%1,%2,%3};"
        : "+f"(c[0]), "+f"(c[1]), "+f"(c[2]), "+f"(c[3])
        : "r"(a[0]), "r"(a[1]), "r"(a[2]), "r"(a[3]), "r"(b0), "r"(b1));
}
__device__ __forceinline__ void mma16816z(float* d, const unsigned* a,
                                          unsigned b0, unsigned b1) {
    asm("mma.sync.aligned.m16n8k16.row.col.f32.bf16.bf16.f32 "
        "{%0,%1,%2,%3}, {%4,%5,%6,%7}, {%8,%9}, {%10,%10,%10,%10};"
        : "=f"(d[0]), "=f"(d[1]), "=f"(d[2]), "=f"(d[3])
        : "r"(a[0]), "r"(a[1]), "r"(a[2]), "r"(a[3]), "r"(b0), "r"(b1), "f"(0.f));
}
// fp16 variant for GEMM2
__device__ __forceinline__ void mma16816h(float* c, const unsigned* a,
                                          unsigned b0, unsigned b1) {
    asm("mma.sync.aligned.m16n8k16.row.col.f32.f16.f16.f32 "
        "{%0,%1,%2,%3}, {%4,%5,%6,%7}, {%8,%9}, {%0,%1,%2,%3};"
        : "+f"(c[0]), "+f"(c[1]), "+f"(c[2]), "+f"(c[3])
        : "r"(a[0]), "r"(a[1]), "r"(a[2]), "r"(a[3]), "r"(b0), "r"(b1));
}

// scalar splitpair (prologue only)
__device__ __forceinline__ void splitpair(float a, float b, unsigned& hi, unsigned& lo) {
    unsigned h;
    asm("cvt.rn.bf16x2.f32 %0, %1, %2;" : "=r"(h) : "f"(b), "f"(a));
    float ra = a - __int_as_float(h << 16);
    float rb = b - __int_as_float(h & 0xFFFF0000u);
    unsigned l;
    asm("cvt.rn.bf16x2.f32 %0, %1, %2;" : "=r"(l) : "f"(rb), "f"(ra));
    hi = h; lo = l;
}

__device__ __forceinline__ float ex2f(float x) {
    float r;
    asm("ex2.approx.ftz.f32 %0, %1;" : "=f"(r) : "f"(x));
    return r;
}

// exp2(c + bias) on SFU + pack pair to f16x2. bias = 14 - rowmax, so the
// max weight is exactly 2^14 (fp16-normal down to 2^-14: 28-bit usable span).
#define EXPH(EH, c0, c1, bias) do {                                          \
    float _e0 = ex2f((c0) + (bias));                                         \
    float _e1 = ex2f((c1) + (bias));                                         \
    asm("cvt.rn.f16x2.f32 %0, %1, %2;" : "=r"(EH) : "f"(_e1), "f"(_e0));     \
} while (0)

// ---- pipelined building blocks ----
// GEMM1 of one 64-codeword chunk into C (24 independent-chain MMAs)
#define GEMM1_CHUNK(cc, C) do {                                              \
    _Pragma("unroll")                                                        \
    for (int j = 0; j < 8; j++) {                                            \
        uint4 B = b1base[((cc) * 64 + 8 * j) * 4];                           \
        mma16816z((C)[j], Ah, B.x, B.y);                                     \
        mma16816 ((C)[j], Ah, B.z, B.w);                                     \
        mma16816 ((C)[j], Al, B.x, B.y);                                     \
    }                                                                        \
} while (0)

// online max + rescale + exp + fp16 GEMM2 for one chunk's C
#define PROCESS_CHUNK(cc, C) do {                                            \
    float mg = fmaxf((C)[0][0], (C)[0][1]);                                  \
    float mh = fmaxf((C)[0][2], (C)[0][3]);                                  \
    _Pragma("unroll")                                                        \
    for (int j = 1; j < 8; j++) {                                            \
        mg = fmaxf(mg, fmaxf((C)[j][0], (C)[j][1]));                         \
        mh = fmaxf(mh, fmaxf((C)[j][2], (C)[j][3]));                         \
    }                                                                        \
    mg = fmaxf(mg, __shfl_xor_sync(0xffffffffu, mg, 1));                     \
    mg = fmaxf(mg, __shfl_xor_sync(0xffffffffu, mg, 2));                     \
    mh = fmaxf(mh, __shfl_xor_sync(0xffffffffu, mh, 1));                     \
    mh = fmaxf(mh, __shfl_xor_sync(0xffffffffu, mh, 2));                     \
    float Mn0 = fmaxf(M0, mg), Mn1 = fmaxf(M1, mh);                          \
    float f0 = ex2f(M0 - Mn0);   /* 0 on first chunk */                      \
    float f1 = ex2f(M1 - Mn1);                                               \
    M0 = Mn0; M1 = Mn1;                                                      \
    const float bb0 = 14.f - M0, bb1 = 14.f - M1;                            \
    D0[0] *= f0; D0[1] *= f0; D1[0] *= f0; D1[1] *= f0;                      \
    D0[2] *= f1; D0[3] *= f1; D1[2] *= f1; D1[3] *= f1;                      \
    _Pragma("unroll")                                                        \
    for (int m = 0; m < 4; m++) {                                            \
        uint4 B2 = b2base[((cc) * 4 + m) * 4];                               \
        unsigned Eh[4];                                                      \
        EXPH(Eh[0], (C)[2*m][0],   (C)[2*m][1],   bb0);                      \
        EXPH(Eh[1], (C)[2*m][2],   (C)[2*m][3],   bb1);                      \
        EXPH(Eh[2], (C)[2*m+1][0], (C)[2*m+1][1], bb0);                      \
        EXPH(Eh[3], (C)[2*m+1][2], (C)[2*m+1][3], bb1);                      \
        mma16816h(D0, Eh, B2.x, B2.y);                                       \
        mma16816h(D1, Eh, B2.z, B2.w);                                       \
    }                                                                        \
} while (0)

// ---------------------------------------------------------------------------
// Main kernel: grid (N/128, 16 books), block 256 (8 warps x 16 rows), 2 CTA/SM.
// ---------------------------------------------------------------------------
__global__ void __launch_bounds__(256, 2)
soft_kernel(const float* __restrict__ feat, const float* __restrict__ alpha_p,
            float* __restrict__ out) {
    __shared__ uint4 s1[KCW * 4];        // 16 KB, stride 64B (conflict-free)
    __shared__ uint4 s2[8 * 68];         // 8.7 KB, d-stride 68*16B (conflict-free)

    const int tid = threadIdx.x;
    const int book = blockIdx.y;

    {
        const uint4* p1 = g_p1 + book * (KCW * 4);
        const uint4* p2 = g_p2 + book * 512;
        for (int i = tid; i < 1024; i += 256) s1[i] = p1[i];
        for (int i = tid; i < 512; i += 256) {
            int d = i >> 6, o = i & 63;          // o = m*4 + ti
            s2[d * 68 + o] = p2[i];
        }
    }
    __syncthreads();

    const float scale = *alpha_p * L2E;       // alpha*log2(e) folded into A
    const int w = tid >> 5, lane = tid & 31;
    const int g = lane >> 2, ti = lane & 3;

    const int row0 = blockIdx.x * 128 + w * 16 + g;      // rows row0, row0+8
    const float* x0 = feat + row0 * FDIM + book * DIMS;
    const float* x1 = x0 + 8 * FDIM;

    // A fragments of (alpha*L2E)*x (split bf16), m16n8k16 layout
    float2 xa = *(const float2*)(x0 + 2 * ti);
    float2 xb = *(const float2*)(x1 + 2 * ti);
    float2 xc = *(const float2*)(x0 + 2 * ti + 8);
    float2 xd = *(const float2*)(x1 + 2 * ti + 8);
    unsigned Ah[4], Al[4];
    splitpair(xa.x * scale, xa.y * scale, Ah[0], Al[0]);
    splitpair(xb.x * scale, xb.y * scale, Ah[1], Al[1]);
    splitpair(xc.x * scale, xc.y * scale, Ah[2], Al[2]);
    splitpair(xd.x * scale, xd.y * scale, Ah[3], Al[3]);

    // Online-softmax state
    float M0 = -1e30f, M1 = -1e30f;
    float D0[4] = {0, 0, 0, 0}, D1[4] = {0, 0, 0, 0};

    const uint4* b1base = s1 + g * 4 + ti;           // + cw*4
    const uint4* b2base = s2 + g * 68 + ti;          // + m*4

    // ---- software-pipelined mainloop (fully unrolled, 2 C blocks) ----
    float Ca[8][4], Cb[8][4];
    GEMM1_CHUNK(0, Ca);
    GEMM1_CHUNK(1, Cb);       // chunk 1 GEMM1 in flight during process(0)
    PROCESS_CHUNK(0, Ca);
    GEMM1_CHUNK(2, Ca);       // chunk 2 in flight during process(1)
    PROCESS_CHUNK(1, Cb);
    GEMM1_CHUNK(3, Cb);       // chunk 3 in flight during process(2)
    PROCESS_CHUNK(2, Ca);
    PROCESS_CHUNK(3, Cb);

    // ---- per-row L2 normalize over 16 dims (softmax denom + 2^(14-M) scale
    //      both cancel) ----
    float ss0 = D0[0] * D0[0] + D0[1] * D0[1] + D1[0] * D1[0] + D1[1] * D1[1];
    float ss1 = D0[2] * D0[2] + D0[3] * D0[3] + D1[2] * D1[2] + D1[3] * D1[3];
    ss0 += __shfl_xor_sync(0xffffffffu, ss0, 1);
    ss0 += __shfl_xor_sync(0xffffffffu, ss0, 2);
    ss1 += __shfl_xor_sync(0xffffffffu, ss1, 1);
    ss1 += __shfl_xor_sync(0xffffffffu, ss1, 2);
    float inv0 = rsqrtf(fmaxf(ss0, 1e-24f));
    float inv1 = rsqrtf(fmaxf(ss1, 1e-24f));

    float* o0 = out + row0 * FDIM + book * DIMS;
    float* o1 = o0 + 8 * FDIM;
    *(float2*)(o0 + 2 * ti)     = make_float2(D0[0] * inv0, D0[1] * inv0);
    *(float2*)(o0 + 2 * ti + 8) = make_float2(D1[0] * inv0, D1[1] * inv0);
    *(float2*)(o1 + 2 * ti)     = make_float2(D0[2] * inv1, D0[3] * inv1);
    *(float2*)(o1 + 2 * ti + 8) = make_float2(D1[2] * inv1, D1[3] * inv1);
}

// ---------------------------------------------------------------------------
extern "C" void kernel_launch(void* const* d_in, const int* in_sizes, int n_in,
                              void* d_out, int out_size) {
    const float* feat    = (const float*)d_in[0];
    const float* Zw      = (const float*)d_in[1];
    const float* alpha_p = (const float*)d_in[3];   // d_in[2] = n_book (unused)
    float* out = (float*)d_out;
    int N = in_sizes[0] / FDIM;

    prep_z_kernel<<<NBOOK, KCW>>>(Zw);
    soft_kernel<<<dim3(N / 128, NBOOK), 256>>>(feat, alpha_p, out);
}

// round 17
// speedup vs baseline: 1.1344x; 1.1344x over previous
#include <cuda_runtime.h>
#include <cuda_bf16.h>
#include <cuda_fp16.h>
#include <cstdint>

// ============================================================================
// softassignment on B200 (sm_100a), round 17 (= round-16 source; round-16
// bench died to an infra container failure before any HW evidence existed).
//   out = intranorm( softmax(alpha*<x_b, zhat_bk>) @ zhat_b )
//   - softmax(a*dot) identity; denominator cancels in final L2 norm.
//   - GEMM2 single fp16 MMA + online row-max rescaling [R13 win: 135.5us]
//   - R15 pipelining reverted (regs 128 -> lost CTA, regressed to 158us).
// Round-16/17 theory — R13/R15 data shows tensor (~6.8K cyc/SMSP/wave, 47%)
// and MUFU (~6.1K, 43%) SUM to the wave time: phase-aligned warps alternate
// the two pipes instead of overlapping them. Two orthogonal fixes:
//   1) ex2.approx.f16x2: ONE MUFU op per logit pair (MUFU halved). Rebias to
//      arg = c - M (top args in [-1,0]: fp16 ulp 2^-11 -> ~2e-4 weight err;
//      max weight = 1 -> weights fp16-normal down to 2^-14 of max).
//   2) per-warp chunk stagger cc = (c + (w&3)) & 3: online rescaling is
//      order-invariant, so this is free; de-phases warps so tensor and MUFU
//      run concurrently across warps.
// ============================================================================

#define NBOOK 16
#define DIMS  16
#define KCW   256
#define FDIM  256
#define L2E   1.4426950408889634f

// g_p1 (GEMM1 B, bf16 hi/lo): [book][cw][ti] 16B, one LDS.128 = 4 fragments.
// g_p2 (GEMM2 B, fp16):       [book][d<8][m][ti] 16B =
//   {f16x2(z[d][16m+2ti..]), f16x2(z[d][16m+2ti+8..]), same for d+8}
__device__ uint4 g_p1[NBOOK * KCW * 4];
__device__ uint4 g_p2[NBOOK * 512];

// ---------------------------------------------------------------------------
__global__ void prep_z_kernel(const float* __restrict__ Zw) {
    int b = blockIdx.x, cw = threadIdx.x;
    const float* src = Zw + cw * FDIM + b * DIMS;
    float v[DIMS], ss = 0.f;
#pragma unroll
    for (int d = 0; d < DIMS; d++) { v[d] = src[d]; ss = fmaf(v[d], v[d], ss); }
    float inv = rsqrtf(fmaxf(ss, 1e-24f));   // == 1/clip(norm,1e-12)
    float z[DIMS];
    __nv_bfloat16 h[DIMS], l[DIMS];
#pragma unroll
    for (int d = 0; d < DIMS; d++) {
        z[d] = v[d] * inv;
        h[d] = __float2bfloat16(z[d]);
        l[d] = __float2bfloat16(z[d] - __bfloat162float(h[d]));
    }
    __nv_bfloat16* p1 = (__nv_bfloat16*)(g_p1 + (b * KCW + cw) * 4);
#pragma unroll
    for (int ti = 0; ti < 4; ti++) {
        p1[ti * 8 + 0] = h[2 * ti];     p1[ti * 8 + 1] = h[2 * ti + 1];
        p1[ti * 8 + 2] = h[2 * ti + 8]; p1[ti * 8 + 3] = h[2 * ti + 9];
        p1[ti * 8 + 4] = l[2 * ti];     p1[ti * 8 + 5] = l[2 * ti + 1];
        p1[ti * 8 + 6] = l[2 * ti + 8]; p1[ti * 8 + 7] = l[2 * ti + 9];
    }
    // GEMM2 fp16 packing: cw = 16m + r; slot = (r&1)+((r>>3)<<1) encodes
    // k-order {2ti, 2ti+1, 2ti+8, 2ti+9}.
    int m = cw >> 4, r = cw & 15;
    int tj = (r >> 1) & 3;
    int slot = (r & 1) + ((r >> 3) << 1);
#pragma unroll
    for (int d = 0; d < 8; d++) {
        __half* q = (__half*)(g_p2 + ((b * 8 + d) * 16 + m) * 4 + tj);
        q[slot]     = __float2half_rn(z[d]);
        q[slot + 4] = __float2half_rn(z[d + 8]);
    }
}

// ---------------------------------------------------------------------------
__device__ __forceinline__ void mma16816(float* c, const unsigned* a,
                                         unsigned b0, unsigned b1) {
    asm("mma.sync.aligned.m16n8k16.row.col.f32.bf16.bf16.f32 "
        "{%0,%1,%2,%3}, {%4,%5,%6,%7}, {%8,%9}, {%0,%1,%2,%3};"
        : "+f"(c[0]), "+f"(c[1]), "+f"(c[2]), "+f"(c[3])
        : "r"(a[0]), "r"(a[1]), "r"(a[2]), "r"(a[3]), "r"(b0), "r"(b1));
}
__device__ __forceinline__ void mma16816z(float* d, const unsigned* a,
                                          unsigned b0, unsigned b1) {
    asm("mma.sync.aligned.m16n8k16.row.col.f32.bf16.bf16.f32 "
        "{%0,%1,%2,%3}, {%4,%5,%6,%7}, {%8,%9}, {%10,%10,%10,%10};"
        : "=f"(d[0]), "=f"(d[1]), "=f"(d[2]), "=f"(d[3])
        : "r"(a[0]), "r"(a[1]), "r"(a[2]), "r"(a[3]), "r"(b0), "r"(b1), "f"(0.f));
}
// fp16 variant for GEMM2
__device__ __forceinline__ void mma16816h(float* c, const unsigned* a,
                                          unsigned b0, unsigned b1) {
    asm("mma.sync.aligned.m16n8k16.row.col.f32.f16.f16.f32 "
        "{%0,%1,%2,%3}, {%4,%5,%6,%7}, {%8,%9}, {%0,%1,%2,%3};"
        : "+f"(c[0]), "+f"(c[1]), "+f"(c[2]), "+f"(c[3])
        : "r"(a[0]), "r"(a[1]), "r"(a[2]), "r"(a[3]), "r"(b0), "r"(b1));
}

// scalar splitpair (prologue only)
__device__ __forceinline__ void splitpair(float a, float b, unsigned& hi, unsigned& lo) {
    unsigned h;
    asm("cvt.rn.bf16x2.f32 %0, %1, %2;" : "=r"(h) : "f"(b), "f"(a));
    float ra = a - __int_as_float(h << 16);
    float rb = b - __int_as_float(h & 0xFFFF0000u);
    unsigned l;
    asm("cvt.rn.bf16x2.f32 %0, %1, %2;" : "=r"(l) : "f"(rb), "f"(ra));
    hi = h; lo = l;
}

__device__ __forceinline__ float ex2f(float x) {
    float r;
    asm("ex2.approx.ftz.f32 %0, %1;" : "=f"(r) : "f"(x));
    return r;
}

// Pair exp2 via ONE fp16x2 MUFU op. bias = -rowmax: top args land in [-1,0]
// (fp16 ulp <= 2^-11 there), max weight = 2^0 = 1 (weights are fp16-normal
// down to 2^-14 of max). Deep-negative args overflow fp16 to -inf/-65504 ->
// ex2 -> 0, harmless (denominator cancels).
#define EXPH(EH, c0, c1, bias) do {                                          \
    float _a0 = (c0) + (bias);                                               \
    float _a1 = (c1) + (bias);                                               \
    unsigned _p;                                                             \
    asm("cvt.rn.f16x2.f32 %0, %1, %2;" : "=r"(_p) : "f"(_a1), "f"(_a0));     \
    asm("ex2.approx.f16x2 %0, %1;" : "=r"(EH) : "r"(_p));                    \
} while (0)

// ---------------------------------------------------------------------------
// Main kernel: grid (N/128, 16 books), block 256 (8 warps x 16 rows), 3 CTA/SM.
// ---------------------------------------------------------------------------
__global__ void __launch_bounds__(256, 3)
soft_kernel(const float* __restrict__ feat, const float* __restrict__ alpha_p,
            float* __restrict__ out) {
    __shared__ uint4 s1[KCW * 4];        // 16 KB, stride 64B (conflict-free)
    __shared__ uint4 s2[8 * 68];         // 8.7 KB, d-stride 68*16B (conflict-free)

    const int tid = threadIdx.x;
    const int book = blockIdx.y;

    {
        const uint4* p1 = g_p1 + book * (KCW * 4);
        const uint4* p2 = g_p2 + book * 512;
        for (int i = tid; i < 1024; i += 256) s1[i] = p1[i];
        for (int i = tid; i < 512; i += 256) {
            int d = i >> 6, o = i & 63;          // o = m*4 + ti
            s2[d * 68 + o] = p2[i];
        }
    }
    __syncthreads();

    const float scale = *alpha_p * L2E;       // alpha*log2(e) folded into A
    const int w = tid >> 5, lane = tid & 31;
    const int g = lane >> 2, ti = lane & 3;

    const int row0 = blockIdx.x * 128 + w * 16 + g;      // rows row0, row0+8
    const float* x0 = feat + row0 * FDIM + book * DIMS;
    const float* x1 = x0 + 8 * FDIM;

    // A fragments of (alpha*L2E)*x (split bf16), m16n8k16 layout
    float2 xa = *(const float2*)(x0 + 2 * ti);
    float2 xb = *(const float2*)(x1 + 2 * ti);
    float2 xc = *(const float2*)(x0 + 2 * ti + 8);
    float2 xd = *(const float2*)(x1 + 2 * ti + 8);
    unsigned Ah[4], Al[4];
    splitpair(xa.x * scale, xa.y * scale, Ah[0], Al[0]);
    splitpair(xb.x * scale, xb.y * scale, Ah[1], Al[1]);
    splitpair(xc.x * scale, xc.y * scale, Ah[2], Al[2]);
    splitpair(xd.x * scale, xd.y * scale, Ah[3], Al[3]);

    // Online-softmax state
    float M0 = -1e30f, M1 = -1e30f;
    float D0[4] = {0, 0, 0, 0}, D1[4] = {0, 0, 0, 0};

    const uint4* b1base = s1 + g * 4 + ti;           // + cw*4
    const uint4* b2base = s2 + g * 68 + ti;          // + m*4

    const int cphase = w & 3;     // per-warp chunk stagger (de-phases pipes)

#pragma unroll 1
    for (int c = 0; c < 4; c++) {
        const int cc = (c + cphase) & 3;
        // ---- GEMM1 chunk: raw log2-logits C[8][4], codewords 64cc..64cc+63 ----
        float C[8][4];
#pragma unroll
        for (int j = 0; j < 8; j++) {
            uint4 B = b1base[(cc * 64 + 8 * j) * 4];
            mma16816z(C[j], Ah, B.x, B.y);   // hi*hi (zero-init)
            mma16816 (C[j], Ah, B.z, B.w);   // hi*lo
            mma16816 (C[j], Al, B.x, B.y);   // lo*hi
        }
        // ---- online max update + accumulator rescale ----
        float mg = fmaxf(C[0][0], C[0][1]);
        float mh = fmaxf(C[0][2], C[0][3]);
#pragma unroll
        for (int j = 1; j < 8; j++) {
            mg = fmaxf(mg, fmaxf(C[j][0], C[j][1]));
            mh = fmaxf(mh, fmaxf(C[j][2], C[j][3]));
        }
        mg = fmaxf(mg, __shfl_xor_sync(0xffffffffu, mg, 1));
        mg = fmaxf(mg, __shfl_xor_sync(0xffffffffu, mg, 2));
        mh = fmaxf(mh, __shfl_xor_sync(0xffffffffu, mh, 1));
        mh = fmaxf(mh, __shfl_xor_sync(0xffffffffu, mh, 2));
        float Mn0 = fmaxf(M0, mg), Mn1 = fmaxf(M1, mh);
        float f0 = ex2f(M0 - Mn0);   // 0 on first chunk (M0=-1e30), D is 0
        float f1 = ex2f(M1 - Mn1);
        M0 = Mn0; M1 = Mn1;
        const float b0 = -M0, b1 = -M1;
        D0[0] *= f0; D0[1] *= f0; D1[0] *= f0; D1[1] *= f0;
        D0[2] *= f1; D0[3] *= f1; D1[2] *= f1; D1[3] *= f1;

        // ---- exp (one fp16x2 MUFU per pair) + single fp16 GEMM2 ----
#pragma unroll
        for (int m = 0; m < 4; m++) {
            uint4 B2 = b2base[(cc * 4 + m) * 4];   // dims g (x,y), g+8 (z,w)
            unsigned Eh[4];
            EXPH(Eh[0], C[2 * m][0],     C[2 * m][1],     b0);  // row g,   k lo
            EXPH(Eh[1], C[2 * m][2],     C[2 * m][3],     b1);  // row g+8, k lo
            EXPH(Eh[2], C[2 * m + 1][0], C[2 * m + 1][1], b0);  // row g,   k hi
            EXPH(Eh[3], C[2 * m + 1][2], C[2 * m + 1][3], b1);  // row g+8, k hi
            mma16816h(D0, Eh, B2.x, B2.y);
            mma16816h(D1, Eh, B2.z, B2.w);
        }
    }

    // ---- per-row L2 normalize over 16 dims (softmax denom + 2^-M scale
    //      both cancel) ----
    float ss0 = D0[0] * D0[0] + D0[1] * D0[1] + D1[0] * D1[0] + D1[1] * D1[1];
    float ss1 = D0[2] * D0[2] + D0[3] * D0[3] + D1[2] * D1[2] + D1[3] * D1[3];
    ss0 += __shfl_xor_sync(0xffffffffu, ss0, 1);
    ss0 += __shfl_xor_sync(0xffffffffu, ss0, 2);
    ss1 += __shfl_xor_sync(0xffffffffu, ss1, 1);
    ss1 += __shfl_xor_sync(0xffffffffu, ss1, 2);
    float inv0 = rsqrtf(fmaxf(ss0, 1e-24f));
    float inv1 = rsqrtf(fmaxf(ss1, 1e-24f));

    float* o0 = out + row0 * FDIM + book * DIMS;
    float* o1 = o0 + 8 * FDIM;
    *(float2*)(o0 + 2 * ti)     = make_float2(D0[0] * inv0, D0[1] * inv0);
    *(float2*)(o0 + 2 * ti + 8) = make_float2(D1[0] * inv0, D1[1] * inv0);
    *(float2*)(o1 + 2 * ti)     = make_float2(D0[2] * inv1, D0[3] * inv1);
    *(float2*)(o1 + 2 * ti + 8) = make_float2(D1[2] * inv1, D1[3] * inv1);
}

// ---------------------------------------------------------------------------
extern "C" void kernel_launch(void* const* d_in, const int* in_sizes, int n_in,
                              void* d_out, int out_size) {
    const float* feat    = (const float*)d_in[0];
    const float* Zw      = (const float*)d_in[1];
    const float* alpha_p = (const float*)d_in[3];   // d_in[2] = n_book (unused)
    float* out = (float*)d_out;
    int N = in_sizes[0] / FDIM;

    prep_z_kernel<<<NBOOK, KCW>>>(Zw);
    soft_kernel<<<dim3(N / 128, NBOOK), 256>>>(feat, alpha_p, out);
}